// round 14
// baseline (speedup 1.0000x reference)
#include <cuda_runtime.h>
#include <cuda_fp16.h>
#include <math.h>

// ---------------------------------------------------------------------------
// Contrast on legacy mma.sync m16n8k16 (baseline PTX; harness targets sm_103).
// All fp16 single-product GEMMs, fp32 accum. CTA 128x128 with 4 warps of
// 64x64 tiles (halved LDSM redundancy), 2-stage cp.async ring, 3 CTAs/SM.
// S fp16 end-to-end, in-place softmax. A/B directions fused per phase.
// ---------------------------------------------------------------------------

namespace {
constexpr int KBLK = 1032;             // u32 words per k16-block: 128*8 + 8 pad
}

// ------------------------------ scratch (u32 words) -------------------------
__device__ unsigned g_Zh [8388608];                   // (za|zb) fp16 16384x1024
__device__ unsigned g_Hh [8388608];                   // H fp16   16384x1024
__device__ unsigned g_Ph [4194304];                   // P fp16   16384x512
__device__ unsigned g_Qh [4194304];                   // Q fp16
__device__ unsigned g_Kh [4194304];                   // K fp16
__device__ unsigned g_Vh [4194304];                   // V fp16
__device__ unsigned g_VT [4194304];                   // V^T fp16 per half [512,8192]
__device__ unsigned g_W1h[524288];                    // W1^T fp16 [1024,1024]
__device__ unsigned g_W2h[262144];                    // W2^T fp16 [512,1024]
__device__ unsigned g_W3h[393216];                    // [Wq;Wk;Wv]^T fp16 [1536,512]
__device__ float    g_bqkv[1536];                     // concat biases
__device__ unsigned g_Sh [67108864];                  // fp16 scores 16384x4096w

// ------------------------------ helpers ------------------------------------
__device__ __forceinline__ void mma_fp16(float* c, const unsigned* a,
                                         unsigned b0, unsigned b1) {
    asm volatile(
        "mma.sync.aligned.m16n8k16.row.col.f32.f16.f16.f32 "
        "{%0,%1,%2,%3}, {%4,%5,%6,%7}, {%8,%9}, {%0,%1,%2,%3};"
        : "+f"(c[0]), "+f"(c[1]), "+f"(c[2]), "+f"(c[3])
        : "r"(a[0]), "r"(a[1]), "r"(a[2]), "r"(a[3]), "r"(b0), "r"(b1));
}

__device__ __forceinline__ void ldsm_x4(unsigned* r, unsigned addr) {
    asm volatile("ldmatrix.sync.aligned.m8n8.x4.shared.b16 {%0,%1,%2,%3}, [%4];"
        : "=r"(r[0]), "=r"(r[1]), "=r"(r[2]), "=r"(r[3]) : "r"(addr));
}

__device__ __forceinline__ void cp16(unsigned dst, const void* src) {
    asm volatile("cp.async.cg.shared.global [%0], [%1], 16;" :: "r"(dst), "l"(src));
}

__device__ __forceinline__ unsigned smem_u32(const void* p) {
    unsigned a;
    asm("{ .reg .u64 t; cvta.to.shared.u64 t, %1; cvt.u32.u64 %0, t; }"
        : "=r"(a) : "l"(p));
    return a;
}

__device__ __forceinline__ unsigned packh2(float x, float y) {
    __half2 h = __floats2half2_rn(x, y);
    return *reinterpret_cast<unsigned*>(&h);
}

// --------------------------- input pack (fp16) ------------------------------
__global__ void __launch_bounds__(256, 8)
pack_in(const float* __restrict__ za, const float* __restrict__ zb,
        unsigned* __restrict__ Zh)
{
    const size_t t = (size_t)blockIdx.x * 256 + threadIdx.x;
    const size_t f = t * 4;
    const float4 v = (f < (size_t)8388608)
        ? *reinterpret_cast<const float4*>(za + f)
        : *reinterpret_cast<const float4*>(zb + (f - 8388608));
    *reinterpret_cast<uint2*>(Zh + t * 2) =
        make_uint2(packh2(v.x, v.y), packh2(v.z, v.w));
}

// ----------------------- weight transpose + fp16 pack -----------------------
__global__ void __launch_bounds__(256, 4)
transpose_packh(const float* __restrict__ src, unsigned* __restrict__ dh, int R, int C)
{
    __shared__ float t[32][33];
    const int bx = blockIdx.x * 32;
    const int by = blockIdx.y * 32;
    const int x  = bx + threadIdx.x;
    #pragma unroll
    for (int i = threadIdx.y; i < 32; i += 8)
        t[i][threadIdx.x] = src[(size_t)(by + i) * C + x];
    __syncthreads();
    const int xo = by + threadIdx.x;
    unsigned short* ph = reinterpret_cast<unsigned short*>(dh);
    #pragma unroll
    for (int i = threadIdx.y; i < 32; i += 8)
        ph[(size_t)(bx + i) * R + xo] =
            __half_as_ushort(__float2half_rn(t[threadIdx.x][i]));
}

// --------------------------- fp16 transpose --------------------------------
__global__ void __launch_bounds__(256, 4)
transpose_h(const unsigned* __restrict__ srcw, unsigned* __restrict__ dstw, int R, int C)
{
    __shared__ unsigned short t[32][34];
    const unsigned short* src = reinterpret_cast<const unsigned short*>(srcw);
    unsigned short* dst = reinterpret_cast<unsigned short*>(dstw);
    const int bx = blockIdx.x * 32;
    const int by = blockIdx.y * 32;
    const int x  = bx + threadIdx.x;
    #pragma unroll
    for (int i = threadIdx.y; i < 32; i += 8)
        t[i][threadIdx.x] = src[(size_t)(by + i) * C + x];
    __syncthreads();
    const int xo = by + threadIdx.x;
    #pragma unroll
    for (int i = threadIdx.y; i < 32; i += 8)
        dst[(size_t)(bx + i) * R + xo] = t[threadIdx.x][i];
}

// ------------------------------ GEMM ---------------------------------------
// C = epi(A[M,K] @ B[N,K]^T), operands fp16-packed (u32 pitch K/2), fp32 accum.
// 128 threads, 4 warps of 64x64; BK=64 (KT=4), 2-stage cp.async ring.
// EPI 0: v*=scale ; EPI 1: v+=bias[col] ; EPI 2: elu(v+bias[col])
// OFMT 0: f32 Cf (+coff) ; OFMT 2: fp16 Ch ; OFMT 4: fp16 Q/K/V triple
// DUAL 0: none ; 1: second M-half uses Bh2 ; 2: second M-half Bh2+coff2, rows fold
template <int EPI, int OFMT, int DUAL>
__global__ void __launch_bounds__(128, 3)
gemm_mm(const unsigned* __restrict__ Ah, const unsigned* __restrict__ Bh,
        const float* __restrict__ bias,
        float* __restrict__ Cf, unsigned* __restrict__ Ch, unsigned* __restrict__ Cl,
        unsigned* __restrict__ Cv,
        int M, int N, int K, int ldc, int coff, float scale,
        const unsigned* __restrict__ Bh2, int coff2)
{
    constexpr int KT = 4;
    extern __shared__ unsigned sm[];
    const unsigned tilesb = smem_u32(sm);
    constexpr unsigned SLBK  = (unsigned)KT * KBLK * 4u;   // 16512 B per half
    constexpr unsigned YOFFB = SLBK;
    constexpr unsigned BUFB  = 2u * SLBK;                  // 33024 B per stage

    const int tid  = threadIdx.x;
    const int bm   = blockIdx.y * 128;
    const int bn   = blockIdx.x * 128;
    const int warp = tid >> 5;
    const int lane = tid & 31;
    const int wm   = (warp >> 1) * 64;
    const int wn   = (warp & 1) * 64;
    const int g    = lane >> 2;
    const int t2   = (lane & 3) * 2;

    const bool second = (DUAL != 0) && (bm >= (M >> 1));
    const unsigned* Bu = second ? Bh2 : Bh;
    const int co    = (DUAL == 2 && second) ? coff2 : coff;
    const int rfold = (DUAL == 2 && second) ? (M >> 1) : 0;

    // ldmatrix relative addresses (stage 0, k-block 0)
    const int mi = lane >> 3;
    const int rl = (lane & 7) + ((mi & 1) << 3);
    const int kg = mi >> 1;
    unsigned relA[4], relB[4];
    #pragma unroll
    for (int mf = 0; mf < 4; mf++) {
        const int row = wm + mf * 16 + rl;
        const int w   = (kg << 2) ^ (((row >> 2) & 1) << 2);
        relA[mf] = tilesb + 4u * (unsigned)(row * 8 + w);
    }
    #pragma unroll
    for (int p = 0; p < 4; p++) {
        const int nf  = 2 * p + (mi >> 1);
        const int row = wn + nf * 8 + (lane & 7);
        const int w   = ((mi & 1) << 2) ^ (((row >> 2) & 1) << 2);
        relB[p] = tilesb + YOFFB + 4u * (unsigned)(row * 8 + w);
    }

    // staging: thread -> (chunk = tid&1, rows tid>>1 and +64); 16 cp16/thread
    const int chunk = tid & 1;
    const int row0  = tid >> 1;            // 0..63
    const int kw    = K >> 1;

    float acc[4][8][4];
    #pragma unroll
    for (int i = 0; i < 4; i++)
        #pragma unroll
        for (int j = 0; j < 8; j++)
            #pragma unroll
            for (int e = 0; e < 4; e++) acc[i][j][e] = 0.f;

    auto stage = [&](int kt, unsigned bufb) {
        #pragma unroll
        for (int i = 0; i < 2; i++) {
            const int row = row0 + 64 * i;
            const int sw  = (chunk * 4) ^ (((row >> 2) & 1) * 4);
            const size_t ga = (size_t)(bm + row) * kw;
            const size_t gb = (size_t)(bn + row) * kw;
            #pragma unroll
            for (int blk = 0; blk < 4; blk++) {
                const unsigned sidx = (unsigned)(blk * KBLK + row * 8 + sw);
                const int gw = kt * 32 + blk * 8 + chunk * 4;
                cp16(tilesb + bufb + 4u * sidx,         Ah + ga + gw);
                cp16(tilesb + bufb + 4u * sidx + YOFFB, Bu + gb + gw);
            }
        }
        asm volatile("cp.async.commit_group;" ::: "memory");
    };

    auto compute = [&](unsigned bufb) {
        #pragma unroll
        for (int blk = 0; blk < KT; blk++) {
            const unsigned off = bufb + (unsigned)(blk * (KBLK * 4));
            unsigned a[4][4], b[4][4];
            #pragma unroll
            for (int mf = 0; mf < 4; mf++) ldsm_x4(a[mf], relA[mf] + off);
            #pragma unroll
            for (int p = 0; p < 4; p++)    ldsm_x4(b[p],  relB[p] + off);
            #pragma unroll
            for (int mf = 0; mf < 4; mf++)
                #pragma unroll
                for (int nf = 0; nf < 8; nf++)
                    mma_fp16(acc[mf][nf], a[mf],
                             b[nf >> 1][(nf & 1) * 2], b[nf >> 1][(nf & 1) * 2 + 1]);
        }
    };

    const int ktiles = K / (16 * KT);
    stage(0, 0u);
    for (int kt = 0; kt < ktiles; kt++) {
        asm volatile("cp.async.wait_group 0;" ::: "memory");
        __syncthreads();
        if (kt + 1 < ktiles) stage(kt + 1, (unsigned)((kt + 1) & 1) * BUFB);
        compute((unsigned)(kt & 1) * BUFB);
    }

    // epilogue
    #pragma unroll
    for (int mf = 0; mf < 4; mf++) {
        #pragma unroll
        for (int nf = 0; nf < 8; nf++) {
            const int row = bm + wm + mf * 16 + g - rfold;
            const int col = bn + wn + nf * 8 + t2;
            float v0 = acc[mf][nf][0], v1 = acc[mf][nf][1];
            float v2 = acc[mf][nf][2], v3 = acc[mf][nf][3];
            if (EPI == 0) {
                v0 *= scale; v1 *= scale; v2 *= scale; v3 *= scale;
            } else {
                const float bb0 = bias[col], bb1 = bias[col + 1];
                v0 += bb0; v1 += bb1; v2 += bb0; v3 += bb1;
                if (EPI == 2) {
                    v0 = v0 > 0.f ? v0 : __expf(v0) - 1.f;
                    v1 = v1 > 0.f ? v1 : __expf(v1) - 1.f;
                    v2 = v2 > 0.f ? v2 : __expf(v2) - 1.f;
                    v3 = v3 > 0.f ? v3 : __expf(v3) - 1.f;
                }
            }
            if (OFMT == 0) {
                *reinterpret_cast<float2*>(Cf + (size_t)row * ldc + co + col)       = make_float2(v0, v1);
                *reinterpret_cast<float2*>(Cf + (size_t)(row + 8) * ldc + co + col) = make_float2(v2, v3);
            } else if (OFMT == 2) {
                Ch[(size_t)row * ldc + (col >> 1)]       = packh2(v0, v1);
                Ch[(size_t)(row + 8) * ldc + (col >> 1)] = packh2(v2, v3);
            } else {    // OFMT 4: Q/K/V triple by global column
                unsigned* dst; int cc;
                if (col < 512)       { dst = Ch; cc = col; }
                else if (col < 1024) { dst = Cl; cc = col - 512; }
                else                 { dst = Cv; cc = col - 1024; }
                dst[(size_t)row * ldc + (cc >> 1)]       = packh2(v0, v1);
                dst[(size_t)(row + 8) * ldc + (cc >> 1)] = packh2(v2, v3);
            }
        }
    }
}

// ------------------- softmax (fp16 in-place, folded scale) ------------------
__global__ void __launch_bounds__(256, 1)
softmax_h(unsigned* __restrict__ Sh, float inv_scale)
{
    const int row = blockIdx.x;
    uint4* p = reinterpret_cast<uint4*>(Sh + (size_t)row * 4096);
    const int tid = threadIdx.x;

    uint4 w[4];
    #pragma unroll
    for (int i = 0; i < 4; i++) w[i] = p[tid + 256 * i];

    float f[32];
    #pragma unroll
    for (int i = 0; i < 4; i++) {
        const unsigned* u = reinterpret_cast<const unsigned*>(&w[i]);
        #pragma unroll
        for (int j = 0; j < 4; j++) {
            float2 d = __half22float2(*reinterpret_cast<const __half2*>(&u[j]));
            f[i * 8 + j * 2]     = d.x;
            f[i * 8 + j * 2 + 1] = d.y;
        }
    }

    float m = -3.402823e38f;
    #pragma unroll
    for (int i = 0; i < 32; i++) m = fmaxf(m, f[i]);

    __shared__ float red[8];
    #pragma unroll
    for (int o = 16; o; o >>= 1) m = fmaxf(m, __shfl_xor_sync(0xffffffffu, m, o));
    if ((tid & 31) == 0) red[tid >> 5] = m;
    __syncthreads();
    float mm = red[0];
    #pragma unroll
    for (int i = 1; i < 8; i++) mm = fmaxf(mm, red[i]);

    float s = 0.f;
    #pragma unroll
    for (int i = 0; i < 32; i++) { f[i] = __expf((f[i] - mm) * inv_scale); s += f[i]; }
    #pragma unroll
    for (int o = 16; o; o >>= 1) s += __shfl_xor_sync(0xffffffffu, s, o);
    __syncthreads();
    if ((tid & 31) == 0) red[tid >> 5] = s;
    __syncthreads();
    float st = 0.f;
    #pragma unroll
    for (int i = 0; i < 8; i++) st += red[i];
    const float inv = 1.0f / st;

    #pragma unroll
    for (int i = 0; i < 4; i++) {
        unsigned* u = reinterpret_cast<unsigned*>(&w[i]);
        #pragma unroll
        for (int j = 0; j < 4; j++)
            u[j] = packh2(f[i * 8 + j * 2] * inv, f[i * 8 + j * 2 + 1] * inv);
    }
    #pragma unroll
    for (int i = 0; i < 4; i++) p[tid + 256 * i] = w[i];
}

// ------------------------------ launcher -----------------------------------
extern "C" void kernel_launch(void* const* d_in, const int* in_sizes, int n_in,
                              void* d_out, int out_size)
{
    const float* za = (const float*)d_in[0];
    const float* zb = (const float*)d_in[1];
    const float* W1 = (const float*)d_in[2];
    const float* b1 = (const float*)d_in[3];
    const float* W2 = (const float*)d_in[4];
    const float* b2 = (const float*)d_in[5];
    const float* Wq = (const float*)d_in[6];
    const float* bq = (const float*)d_in[7];
    const float* Wk = (const float*)d_in[8];
    const float* bk = (const float*)d_in[9];
    const float* Wv = (const float*)d_in[10];
    const float* bv = (const float*)d_in[11];
    float* out = (float*)d_out;

    unsigned *Zh, *Hh, *Ph, *Qh, *Kh, *Vh, *VT, *W1h, *W2h, *W3h, *Sh;
    float *bqkv;
    cudaGetSymbolAddress((void**)&Zh,  g_Zh);
    cudaGetSymbolAddress((void**)&Hh,  g_Hh);  cudaGetSymbolAddress((void**)&Ph,  g_Ph);
    cudaGetSymbolAddress((void**)&Qh,  g_Qh);  cudaGetSymbolAddress((void**)&Kh,  g_Kh);
    cudaGetSymbolAddress((void**)&Vh,  g_Vh);  cudaGetSymbolAddress((void**)&VT,  g_VT);
    cudaGetSymbolAddress((void**)&W1h, g_W1h); cudaGetSymbolAddress((void**)&W2h, g_W2h);
    cudaGetSymbolAddress((void**)&W3h, g_W3h);
    cudaGetSymbolAddress((void**)&Sh,  g_Sh);  cudaGetSymbolAddress((void**)&bqkv, g_bqkv);

    const int smem_g = 2 * 2 * (4 * KBLK * 4);   // 66048 B (2-stage ring)
    cudaFuncSetAttribute(gemm_mm<2,2,0>, cudaFuncAttributeMaxDynamicSharedMemorySize, smem_g);
    cudaFuncSetAttribute(gemm_mm<1,2,0>, cudaFuncAttributeMaxDynamicSharedMemorySize, smem_g);
    cudaFuncSetAttribute(gemm_mm<1,4,0>, cudaFuncAttributeMaxDynamicSharedMemorySize, smem_g);
    cudaFuncSetAttribute(gemm_mm<0,2,1>, cudaFuncAttributeMaxDynamicSharedMemorySize, smem_g);
    cudaFuncSetAttribute(gemm_mm<0,0,2>, cudaFuncAttributeMaxDynamicSharedMemorySize, smem_g);

    const dim3 gblk(128);
    const dim3 blk(256);
    const dim3 tblk(32, 8);
    const float inv_scale = 1.0f / 16.0f;   // 1/sqrt(OUT/2)
    const size_t HALFW = (size_t)8192 * 256;   // half of Q/K/V word arrays
    const size_t HVTW  = (size_t)512 * 4096;   // half of VT

    // kernel launches 1-3 (capture slot #4 = L1 GEMM)
    pack_in<<<16384, blk>>>(za, zb, Zh);
    transpose_packh<<<dim3(32, 32), tblk>>>(W1, W1h, 1024, 1024);
    transpose_packh<<<dim3(16, 32), tblk>>>(W2, W2h, 1024, 512);

    // #4: proj L1: H = ELU(Z @ W1^T + b1), fp16 out   [16384 x 1024]
    gemm_mm<2,2,0><<<dim3(8, 128), gblk, smem_g>>>(
        Zh, W1h, b1, nullptr, Hh, nullptr, nullptr,
        16384, 1024, 1024, 512, 0, 1.f, nullptr, 0);

    // QKV weight concat transposes + bias concat
    transpose_packh<<<dim3(16, 16), tblk>>>(Wq, W3h,          512, 512);
    transpose_packh<<<dim3(16, 16), tblk>>>(Wk, W3h + 131072, 512, 512);
    transpose_packh<<<dim3(16, 16), tblk>>>(Wv, W3h + 262144, 512, 512);
    cudaMemcpyAsync(bqkv,        bq, 512 * sizeof(float), cudaMemcpyDeviceToDevice);
    cudaMemcpyAsync(bqkv + 512,  bk, 512 * sizeof(float), cudaMemcpyDeviceToDevice);
    cudaMemcpyAsync(bqkv + 1024, bv, 512 * sizeof(float), cudaMemcpyDeviceToDevice);

    // proj L2: P = H @ W2^T + b2, fp16 out            [16384 x 512]
    gemm_mm<1,2,0><<<dim3(4, 128), gblk, smem_g>>>(
        Hh, W2h, b2, nullptr, Ph, nullptr, nullptr,
        16384, 512, 1024, 256, 0, 1.f, nullptr, 0);

    // fused QKV: [Q|K|V] = P @ [Wq;Wk;Wv]^T + bqkv    [16384 x 1536]
    gemm_mm<1,4,0><<<dim3(12, 128), gblk, smem_g>>>(
        Ph, W3h, bqkv, nullptr, Qh, Kh, Vh,
        16384, 1536, 512, 256, 0, 1.f, nullptr, 0);

    // V^T per half (fp16)
    transpose_h<<<dim3(16, 256), tblk>>>(Vh,         VT,        8192, 512);
    transpose_h<<<dim3(16, 256), tblk>>>(Vh + HALFW, VT + HVTW, 8192, 512);

    // fused scores (fp16 raw logits): rows 0-8191 = Qa@Kb^T, rows 8192.. = Qb@Ka^T
    gemm_mm<0,2,1><<<dim3(64, 128), gblk, smem_g>>>(
        Qh, Kh + HALFW, nullptr, nullptr, Sh, nullptr, nullptr,
        16384, 8192, 512, 4096, 0, 1.f, Kh, 0);
    // fused in-place fp16 softmax (scale folded into exp)
    softmax_h<<<16384, blk>>>(Sh, inv_scale);
    // fused AV: rows 0-8191 -> out[:,0:512] (Vb), rows 8192-16383 -> out[:,512:1024] (Va)
    gemm_mm<0,0,2><<<dim3(4, 128), gblk, smem_g>>>(
        Sh, VT + HVTW, nullptr, out, nullptr, nullptr, nullptr,
        16384, 512, 8192, 1024, 0, 1.f, VT, 512);
}

// round 15
// speedup vs baseline: 1.0693x; 1.0693x over previous
#include <cuda_runtime.h>
#include <cuda_fp16.h>
#include <math.h>

// ---------------------------------------------------------------------------
// Contrast on legacy mma.sync m16n8k16 (baseline PTX; harness targets sm_103).
// Round-13 kernels (proven): fp16 single-product GEMMs, fp32 accum, BK=64
// 3-stage cp.async ring, 8 warps x 64x32 tiles, 2 CTAs/SM. S fp16 in-place
// softmax. NEW: attention directions A/B run on forked streams so the
// memory-bound softmax overlaps the other direction's tensor-bound GEMMs.
// ---------------------------------------------------------------------------

namespace {
constexpr int KBLK = 1032;             // u32 words per k16-block: 128*8 + 8 pad
}

// ------------------------------ scratch (u32 words) -------------------------
__device__ unsigned g_Zh [8388608];                   // (za|zb) fp16 16384x1024
__device__ unsigned g_Hh [8388608];                   // H fp16   16384x1024
__device__ unsigned g_Ph [4194304];                   // P fp16   16384x512
__device__ unsigned g_Qh [4194304];                   // Q fp16
__device__ unsigned g_Kh [4194304];                   // K fp16
__device__ unsigned g_Vh [4194304];                   // V fp16
__device__ unsigned g_VT [4194304];                   // V^T fp16 per half [512,8192]
__device__ unsigned g_W1h[524288];                    // W1^T fp16 [1024,1024]
__device__ unsigned g_W2h[262144];                    // W2^T fp16 [512,1024]
__device__ unsigned g_W3h[393216];                    // [Wq;Wk;Wv]^T fp16 [1536,512]
__device__ float    g_bqkv[1536];                     // concat biases
__device__ unsigned g_Sh [67108864];                  // fp16 scores 16384x4096w

// ------------------------------ helpers ------------------------------------
__device__ __forceinline__ void mma_fp16(float* c, const unsigned* a,
                                         unsigned b0, unsigned b1) {
    asm volatile(
        "mma.sync.aligned.m16n8k16.row.col.f32.f16.f16.f32 "
        "{%0,%1,%2,%3}, {%4,%5,%6,%7}, {%8,%9}, {%0,%1,%2,%3};"
        : "+f"(c[0]), "+f"(c[1]), "+f"(c[2]), "+f"(c[3])
        : "r"(a[0]), "r"(a[1]), "r"(a[2]), "r"(a[3]), "r"(b0), "r"(b1));
}

__device__ __forceinline__ void ldsm_x4(unsigned* r, unsigned addr) {
    asm volatile("ldmatrix.sync.aligned.m8n8.x4.shared.b16 {%0,%1,%2,%3}, [%4];"
        : "=r"(r[0]), "=r"(r[1]), "=r"(r[2]), "=r"(r[3]) : "r"(addr));
}

__device__ __forceinline__ void cp16(unsigned dst, const void* src) {
    asm volatile("cp.async.cg.shared.global [%0], [%1], 16;" :: "r"(dst), "l"(src));
}

__device__ __forceinline__ unsigned smem_u32(const void* p) {
    unsigned a;
    asm("{ .reg .u64 t; cvta.to.shared.u64 t, %1; cvt.u32.u64 %0, t; }"
        : "=r"(a) : "l"(p));
    return a;
}

__device__ __forceinline__ unsigned packh2(float x, float y) {
    __half2 h = __floats2half2_rn(x, y);
    return *reinterpret_cast<unsigned*>(&h);
}

// --------------------------- input pack (fp16) ------------------------------
__global__ void __launch_bounds__(256, 8)
pack_in(const float* __restrict__ za, const float* __restrict__ zb,
        unsigned* __restrict__ Zh)
{
    const size_t t = (size_t)blockIdx.x * 256 + threadIdx.x;
    const size_t f = t * 4;
    const float4 v = (f < (size_t)8388608)
        ? *reinterpret_cast<const float4*>(za + f)
        : *reinterpret_cast<const float4*>(zb + (f - 8388608));
    *reinterpret_cast<uint2*>(Zh + t * 2) =
        make_uint2(packh2(v.x, v.y), packh2(v.z, v.w));
}

// ----------------------- weight transpose + fp16 pack -----------------------
__global__ void __launch_bounds__(256, 4)
transpose_packh(const float* __restrict__ src, unsigned* __restrict__ dh, int R, int C)
{
    __shared__ float t[32][33];
    const int bx = blockIdx.x * 32;
    const int by = blockIdx.y * 32;
    const int x  = bx + threadIdx.x;
    #pragma unroll
    for (int i = threadIdx.y; i < 32; i += 8)
        t[i][threadIdx.x] = src[(size_t)(by + i) * C + x];
    __syncthreads();
    const int xo = by + threadIdx.x;
    unsigned short* ph = reinterpret_cast<unsigned short*>(dh);
    #pragma unroll
    for (int i = threadIdx.y; i < 32; i += 8)
        ph[(size_t)(bx + i) * R + xo] =
            __half_as_ushort(__float2half_rn(t[threadIdx.x][i]));
}

// --------------------------- fp16 transpose --------------------------------
__global__ void __launch_bounds__(256, 4)
transpose_h(const unsigned* __restrict__ srcw, unsigned* __restrict__ dstw, int R, int C)
{
    __shared__ unsigned short t[32][34];
    const unsigned short* src = reinterpret_cast<const unsigned short*>(srcw);
    unsigned short* dst = reinterpret_cast<unsigned short*>(dstw);
    const int bx = blockIdx.x * 32;
    const int by = blockIdx.y * 32;
    const int x  = bx + threadIdx.x;
    #pragma unroll
    for (int i = threadIdx.y; i < 32; i += 8)
        t[i][threadIdx.x] = src[(size_t)(by + i) * C + x];
    __syncthreads();
    const int xo = by + threadIdx.x;
    #pragma unroll
    for (int i = threadIdx.y; i < 32; i += 8)
        dst[(size_t)(bx + i) * R + xo] = t[threadIdx.x][i];
}

// ------------------------------ GEMM ---------------------------------------
// C = epi(A[M,K] @ B[N,K]^T), operands fp16-packed (u32 pitch K/2), fp32 accum.
// 256 threads, 8 warps of 64x32; BK=64 (KT=4), 3-stage cp.async ring.
// EPI 0: v*=scale ; EPI 1: v+=bias[col] ; EPI 2: elu(v+bias[col])
// OFMT 0: f32 Cf (+coff) ; OFMT 2: fp16 Ch ; OFMT 4: fp16 Q/K/V triple
// DUAL 0: none (directions handled by separate launches this round)
template <int EPI, int OFMT, int DUAL>
__global__ void __launch_bounds__(256, 2)
gemm_mm(const unsigned* __restrict__ Ah, const unsigned* __restrict__ Bh,
        const float* __restrict__ bias,
        float* __restrict__ Cf, unsigned* __restrict__ Ch, unsigned* __restrict__ Cl,
        unsigned* __restrict__ Cv,
        int M, int N, int K, int ldc, int coff, float scale,
        const unsigned* __restrict__ Bh2, int coff2)
{
    constexpr int KT = 4;
    extern __shared__ unsigned sm[];
    const unsigned tilesb = smem_u32(sm);
    constexpr unsigned SLBK  = (unsigned)KT * KBLK * 4u;   // 16512 B per half
    constexpr unsigned YOFFB = SLBK;
    constexpr unsigned BUFB  = 2u * SLBK;

    const int tid  = threadIdx.x;
    const int bm   = blockIdx.y * 128;
    const int bn   = blockIdx.x * 128;
    const int warp = tid >> 5;
    const int lane = tid & 31;
    const int wm   = (warp >> 2) * 64;
    const int wn   = (warp & 3) * 32;
    const int g    = lane >> 2;
    const int t2   = (lane & 3) * 2;

    const bool second = (DUAL != 0) && (bm >= (M >> 1));
    const unsigned* Bu = second ? Bh2 : Bh;
    const int co    = (DUAL == 2 && second) ? coff2 : coff;
    const int rfold = (DUAL == 2 && second) ? (M >> 1) : 0;

    // ldmatrix relative addresses (stage 0, k-block 0)
    const int mi = lane >> 3;
    const int rl = (lane & 7) + ((mi & 1) << 3);
    const int kg = mi >> 1;
    unsigned relA[4], relB[2];
    #pragma unroll
    for (int mf = 0; mf < 4; mf++) {
        const int row = wm + mf * 16 + rl;
        const int w   = (kg << 2) ^ (((row >> 2) & 1) << 2);
        relA[mf] = tilesb + 4u * (unsigned)(row * 8 + w);
    }
    #pragma unroll
    for (int p = 0; p < 2; p++) {
        const int nf  = 2 * p + (mi >> 1);
        const int row = wn + nf * 8 + (lane & 7);
        const int w   = ((mi & 1) << 2) ^ (((row >> 2) & 1) << 2);
        relB[p] = tilesb + YOFFB + 4u * (unsigned)(row * 8 + w);
    }

    // staging mapping: 8 threads per 128-row, 4 row-passes of 32 rows
    constexpr int TPR     = 2 * KT;                // 8
    constexpr int RSTRIDE = 128 / KT;              // 32
    constexpr unsigned PBYTES = (unsigned)RSTRIDE * 32u;  // 1024
    const int srow  = tid / TPR;
    const int scol8 = (tid % TPR) * 8;
    const int sblk  = scol8 >> 4;
    const int sw0   = ((scol8 & 15) >> 1) ^ (((srow >> 2) & 1) * 4);
    const unsigned sidx0 = (unsigned)(sblk * KBLK + srow * 8 + sw0);
    const int kw = K >> 1;

    float acc[4][4][4];
    #pragma unroll
    for (int i = 0; i < 4; i++)
        #pragma unroll
        for (int j = 0; j < 4; j++)
            #pragma unroll
            for (int e = 0; e < 4; e++) acc[i][j][e] = 0.f;

    auto stage = [&](int kt, unsigned bufb) {
        const int w0 = kt * (8 * KT) + (scol8 >> 1);
        const unsigned d0 = tilesb + bufb + 4u * sidx0;
        #pragma unroll
        for (int i = 0; i < KT; i++)
            cp16(d0 + PBYTES * i, Ah + (size_t)(bm + srow + RSTRIDE * i) * kw + w0);
        #pragma unroll
        for (int i = 0; i < KT; i++)
            cp16(d0 + PBYTES * i + YOFFB, Bu + (size_t)(bn + srow + RSTRIDE * i) * kw + w0);
        asm volatile("cp.async.commit_group;" ::: "memory");
    };

    auto compute = [&](unsigned bufb) {
        #pragma unroll
        for (int blk = 0; blk < KT; blk++) {
            const unsigned off = bufb + (unsigned)(blk * (KBLK * 4));
            unsigned a[4][4], b[2][4];
            #pragma unroll
            for (int mf = 0; mf < 4; mf++) ldsm_x4(a[mf], relA[mf] + off);
            #pragma unroll
            for (int p = 0; p < 2; p++)    ldsm_x4(b[p],  relB[p] + off);
            #pragma unroll
            for (int mf = 0; mf < 4; mf++)
                #pragma unroll
                for (int nf = 0; nf < 4; nf++)
                    mma_fp16(acc[mf][nf], a[mf],
                             b[nf >> 1][(nf & 1) * 2], b[nf >> 1][(nf & 1) * 2 + 1]);
        }
    };

    const int ktiles = K / (16 * KT);
    stage(0, 0u);
    stage(1, BUFB);
    for (int kt = 0; kt < ktiles; kt++) {
        if (kt + 1 < ktiles) asm volatile("cp.async.wait_group 1;" ::: "memory");
        else                 asm volatile("cp.async.wait_group 0;" ::: "memory");
        __syncthreads();
        if (kt + 2 < ktiles) stage(kt + 2, (unsigned)((kt + 2) % 3) * BUFB);
        compute((unsigned)(kt % 3) * BUFB);
    }

    // epilogue
    #pragma unroll
    for (int mf = 0; mf < 4; mf++) {
        #pragma unroll
        for (int nf = 0; nf < 4; nf++) {
            const int row = bm + wm + mf * 16 + g - rfold;
            const int col = bn + wn + nf * 8 + t2;
            float v0 = acc[mf][nf][0], v1 = acc[mf][nf][1];
            float v2 = acc[mf][nf][2], v3 = acc[mf][nf][3];
            if (EPI == 0) {
                v0 *= scale; v1 *= scale; v2 *= scale; v3 *= scale;
            } else {
                const float bb0 = bias[col], bb1 = bias[col + 1];
                v0 += bb0; v1 += bb1; v2 += bb0; v3 += bb1;
                if (EPI == 2) {
                    v0 = v0 > 0.f ? v0 : __expf(v0) - 1.f;
                    v1 = v1 > 0.f ? v1 : __expf(v1) - 1.f;
                    v2 = v2 > 0.f ? v2 : __expf(v2) - 1.f;
                    v3 = v3 > 0.f ? v3 : __expf(v3) - 1.f;
                }
            }
            if (OFMT == 0) {
                *reinterpret_cast<float2*>(Cf + (size_t)row * ldc + co + col)       = make_float2(v0, v1);
                *reinterpret_cast<float2*>(Cf + (size_t)(row + 8) * ldc + co + col) = make_float2(v2, v3);
            } else if (OFMT == 2) {
                Ch[(size_t)row * ldc + (col >> 1)]       = packh2(v0, v1);
                Ch[(size_t)(row + 8) * ldc + (col >> 1)] = packh2(v2, v3);
            } else {    // OFMT 4: Q/K/V triple by global column
                unsigned* dst; int cc;
                if (col < 512)       { dst = Ch; cc = col; }
                else if (col < 1024) { dst = Cl; cc = col - 512; }
                else                 { dst = Cv; cc = col - 1024; }
                dst[(size_t)row * ldc + (cc >> 1)]       = packh2(v0, v1);
                dst[(size_t)(row + 8) * ldc + (cc >> 1)] = packh2(v2, v3);
            }
        }
    }
}

// ------------------- softmax (fp16 in-place, folded scale) ------------------
__global__ void __launch_bounds__(256, 1)
softmax_h(unsigned* __restrict__ Sh, float inv_scale)
{
    const int row = blockIdx.x;
    uint4* p = reinterpret_cast<uint4*>(Sh + (size_t)row * 4096);
    const int tid = threadIdx.x;

    uint4 w[4];
    #pragma unroll
    for (int i = 0; i < 4; i++) w[i] = p[tid + 256 * i];

    float f[32];
    #pragma unroll
    for (int i = 0; i < 4; i++) {
        const unsigned* u = reinterpret_cast<const unsigned*>(&w[i]);
        #pragma unroll
        for (int j = 0; j < 4; j++) {
            float2 d = __half22float2(*reinterpret_cast<const __half2*>(&u[j]));
            f[i * 8 + j * 2]     = d.x;
            f[i * 8 + j * 2 + 1] = d.y;
        }
    }

    float m = -3.402823e38f;
    #pragma unroll
    for (int i = 0; i < 32; i++) m = fmaxf(m, f[i]);

    __shared__ float red[8];
    #pragma unroll
    for (int o = 16; o; o >>= 1) m = fmaxf(m, __shfl_xor_sync(0xffffffffu, m, o));
    if ((tid & 31) == 0) red[tid >> 5] = m;
    __syncthreads();
    float mm = red[0];
    #pragma unroll
    for (int i = 1; i < 8; i++) mm = fmaxf(mm, red[i]);

    float s = 0.f;
    #pragma unroll
    for (int i = 0; i < 32; i++) { f[i] = __expf((f[i] - mm) * inv_scale); s += f[i]; }
    #pragma unroll
    for (int o = 16; o; o >>= 1) s += __shfl_xor_sync(0xffffffffu, s, o);
    __syncthreads();
    if ((tid & 31) == 0) red[tid >> 5] = s;
    __syncthreads();
    float st = 0.f;
    #pragma unroll
    for (int i = 0; i < 8; i++) st += red[i];
    const float inv = 1.0f / st;

    #pragma unroll
    for (int i = 0; i < 4; i++) {
        unsigned* u = reinterpret_cast<unsigned*>(&w[i]);
        #pragma unroll
        for (int j = 0; j < 4; j++)
            u[j] = packh2(f[i * 8 + j * 2] * inv, f[i * 8 + j * 2 + 1] * inv);
    }
    #pragma unroll
    for (int i = 0; i < 4; i++) p[tid + 256 * i] = w[i];
}

// ------------------------------ launcher -----------------------------------
extern "C" void kernel_launch(void* const* d_in, const int* in_sizes, int n_in,
                              void* d_out, int out_size)
{
    const float* za = (const float*)d_in[0];
    const float* zb = (const float*)d_in[1];
    const float* W1 = (const float*)d_in[2];
    const float* b1 = (const float*)d_in[3];
    const float* W2 = (const float*)d_in[4];
    const float* b2 = (const float*)d_in[5];
    const float* Wq = (const float*)d_in[6];
    const float* bq = (const float*)d_in[7];
    const float* Wk = (const float*)d_in[8];
    const float* bk = (const float*)d_in[9];
    const float* Wv = (const float*)d_in[10];
    const float* bv = (const float*)d_in[11];
    float* out = (float*)d_out;

    unsigned *Zh, *Hh, *Ph, *Qh, *Kh, *Vh, *VT, *W1h, *W2h, *W3h, *Sh;
    float *bqkv;
    cudaGetSymbolAddress((void**)&Zh,  g_Zh);
    cudaGetSymbolAddress((void**)&Hh,  g_Hh);  cudaGetSymbolAddress((void**)&Ph,  g_Ph);
    cudaGetSymbolAddress((void**)&Qh,  g_Qh);  cudaGetSymbolAddress((void**)&Kh,  g_Kh);
    cudaGetSymbolAddress((void**)&Vh,  g_Vh);  cudaGetSymbolAddress((void**)&VT,  g_VT);
    cudaGetSymbolAddress((void**)&W1h, g_W1h); cudaGetSymbolAddress((void**)&W2h, g_W2h);
    cudaGetSymbolAddress((void**)&W3h, g_W3h);
    cudaGetSymbolAddress((void**)&Sh,  g_Sh);  cudaGetSymbolAddress((void**)&bqkv, g_bqkv);

    // one-time side stream + events (created on the uncaptured correctness
    // call; reused by the capture call via the standard fork/join pattern)
    static cudaStream_t sA = nullptr;
    static cudaEvent_t  evQ = nullptr, evVT = nullptr, evA = nullptr;
    if (sA == nullptr) {
        cudaStreamCreateWithFlags(&sA, cudaStreamNonBlocking);
        cudaEventCreateWithFlags(&evQ,  cudaEventDisableTiming);
        cudaEventCreateWithFlags(&evVT, cudaEventDisableTiming);
        cudaEventCreateWithFlags(&evA,  cudaEventDisableTiming);
    }

    const int smem_g = 3 * 2 * (4 * KBLK * 4);   // 99072 B (3-stage ring)
    cudaFuncSetAttribute(gemm_mm<2,2,0>, cudaFuncAttributeMaxDynamicSharedMemorySize, smem_g);
    cudaFuncSetAttribute(gemm_mm<1,2,0>, cudaFuncAttributeMaxDynamicSharedMemorySize, smem_g);
    cudaFuncSetAttribute(gemm_mm<1,4,0>, cudaFuncAttributeMaxDynamicSharedMemorySize, smem_g);
    cudaFuncSetAttribute(gemm_mm<0,2,0>, cudaFuncAttributeMaxDynamicSharedMemorySize, smem_g);
    cudaFuncSetAttribute(gemm_mm<0,0,0>, cudaFuncAttributeMaxDynamicSharedMemorySize, smem_g);

    const dim3 blk(256);
    const dim3 tblk(32, 8);
    const float inv_scale = 1.0f / 16.0f;      // 1/sqrt(OUT/2)
    const size_t HALFW = (size_t)8192 * 256;   // half of Q/K/V word arrays
    const size_t HVTW  = (size_t)512 * 4096;   // half of VT
    const size_t HSW   = (size_t)8192 * 4096;  // half of Sh

    // kernel launches 1-3 (capture slot #4 = L1 GEMM, control)
    pack_in<<<16384, blk>>>(za, zb, Zh);
    transpose_packh<<<dim3(32, 32), tblk>>>(W1, W1h, 1024, 1024);
    transpose_packh<<<dim3(16, 32), tblk>>>(W2, W2h, 1024, 512);

    // #4: proj L1: H = ELU(Z @ W1^T + b1), fp16 out   [16384 x 1024]
    gemm_mm<2,2,0><<<dim3(8, 128), blk, smem_g>>>(
        Zh, W1h, b1, nullptr, Hh, nullptr, nullptr,
        16384, 1024, 1024, 512, 0, 1.f, nullptr, 0);

    // QKV weight concat transposes + bias concat
    transpose_packh<<<dim3(16, 16), tblk>>>(Wq, W3h,          512, 512);
    transpose_packh<<<dim3(16, 16), tblk>>>(Wk, W3h + 131072, 512, 512);
    transpose_packh<<<dim3(16, 16), tblk>>>(Wv, W3h + 262144, 512, 512);
    cudaMemcpyAsync(bqkv,        bq, 512 * sizeof(float), cudaMemcpyDeviceToDevice);
    cudaMemcpyAsync(bqkv + 512,  bk, 512 * sizeof(float), cudaMemcpyDeviceToDevice);
    cudaMemcpyAsync(bqkv + 1024, bv, 512 * sizeof(float), cudaMemcpyDeviceToDevice);

    // proj L2: P = H @ W2^T + b2, fp16 out            [16384 x 512]
    gemm_mm<1,2,0><<<dim3(4, 128), blk, smem_g>>>(
        Hh, W2h, b2, nullptr, Ph, nullptr, nullptr,
        16384, 512, 1024, 256, 0, 1.f, nullptr, 0);

    // fused QKV: [Q|K|V] = P @ [Wq;Wk;Wv]^T + bqkv    [16384 x 1536]
    gemm_mm<1,4,0><<<dim3(12, 128), blk, smem_g>>>(
        Ph, W3h, bqkv, nullptr, Qh, Kh, Vh,
        16384, 1536, 512, 256, 0, 1.f, nullptr, 0);

    // fork: direction A chain on side stream
    cudaEventRecord(evQ, 0);
    cudaStreamWaitEvent(sA, evQ, 0);

    // --- stream sA: scores A -> softmax A ---
    gemm_mm<0,2,0><<<dim3(64, 64), blk, smem_g, sA>>>(
        Qh, Kh + HALFW, nullptr, nullptr, Sh, nullptr, nullptr,
        8192, 8192, 512, 4096, 0, 1.f, nullptr, 0);
    softmax_h<<<8192, blk, 0, sA>>>(Sh, inv_scale);

    // --- default stream: V^T transposes, then direction B chain ---
    transpose_h<<<dim3(16, 256), tblk>>>(Vh,         VT,        8192, 512);
    transpose_h<<<dim3(16, 256), tblk>>>(Vh + HALFW, VT + HVTW, 8192, 512);
    cudaEventRecord(evVT, 0);

    gemm_mm<0,2,0><<<dim3(64, 64), blk, smem_g>>>(
        Qh + HALFW, Kh, nullptr, nullptr, Sh + HSW, nullptr, nullptr,
        8192, 8192, 512, 4096, 0, 1.f, nullptr, 0);
    softmax_h<<<8192, blk>>>(Sh + HSW, inv_scale);

    // --- stream sA: AV A (needs VT) -> out[:, 0:512] ---
    cudaStreamWaitEvent(sA, evVT, 0);
    gemm_mm<0,0,0><<<dim3(4, 64), blk, smem_g, sA>>>(
        Sh, VT + HVTW, nullptr, out, nullptr, nullptr, nullptr,
        8192, 512, 8192, 1024, 0, 1.f, nullptr, 0);
    cudaEventRecord(evA, sA);

    // --- default stream: AV B -> out[:, 512:1024], then join ---
    gemm_mm<0,0,0><<<dim3(4, 64), blk, smem_g>>>(
        Sh + HSW, VT, nullptr, out, nullptr, nullptr, nullptr,
        8192, 512, 8192, 1024, 512, 1.f, nullptr, 0);
    cudaStreamWaitEvent(0, evA, 0);
}